// round 5
// baseline (speedup 1.0000x reference)
#include <cuda_runtime.h>

// DiffJPEG: per 8x8 block  D @ X @ D^T -> round(./Q)*Q -> D^T @ . @ D
// R5 (= R3 design, third bench attempt; R3/R4 were broker infra failures):
// 8 threads per 8x8 block (one row per lane), column transforms via 8x8
// register transpose using shfl_xor butterfly. ~35 regs/thread -> high
// occupancy so DRAM stays busy (R2 was 2 CTA/SM, latency-bound at 45us).

namespace {

__device__ constexpr float Dm[8][8] = {
    { 0.35355339059327373f,  0.35355339059327373f,  0.35355339059327373f,  0.35355339059327373f,
      0.35355339059327373f,  0.35355339059327373f,  0.35355339059327373f,  0.35355339059327373f },
    { 0.49039264020161522f,  0.41573480615127262f,  0.27778511650980114f,  0.09754516100806412f,
     -0.09754516100806412f, -0.27778511650980114f, -0.41573480615127262f, -0.49039264020161522f },
    { 0.46193976625564337f,  0.19134171618254492f, -0.19134171618254492f, -0.46193976625564337f,
     -0.46193976625564337f, -0.19134171618254492f,  0.19134171618254492f,  0.46193976625564337f },
    { 0.41573480615127262f, -0.09754516100806412f, -0.49039264020161522f, -0.27778511650980114f,
      0.27778511650980114f,  0.49039264020161522f,  0.09754516100806412f, -0.41573480615127262f },
    { 0.35355339059327373f, -0.35355339059327373f, -0.35355339059327373f,  0.35355339059327373f,
      0.35355339059327373f, -0.35355339059327373f, -0.35355339059327373f,  0.35355339059327373f },
    { 0.27778511650980114f, -0.49039264020161522f,  0.09754516100806412f,  0.41573480615127262f,
     -0.41573480615127262f, -0.09754516100806412f,  0.49039264020161522f, -0.27778511650980114f },
    { 0.19134171618254492f, -0.46193976625564337f,  0.46193976625564337f, -0.19134171618254492f,
     -0.19134171618254492f,  0.46193976625564337f, -0.46193976625564337f,  0.19134171618254492f },
    { 0.09754516100806412f, -0.27778511650980114f,  0.41573480615127262f, -0.49039264020161522f,
      0.49039264020161522f, -0.41573480615127262f,  0.27778511650980114f, -0.09754516100806412f }
};

// Q^T (quality=50 -> Q = q_luma exactly). Row c holds Q[0..7][c].
__device__ const float QTq[8][8] = {
    {16.f, 12.f, 14.f, 14.f, 18.f, 24.f, 49.f, 72.f},
    {11.f, 12.f, 13.f, 17.f, 22.f, 35.f, 64.f, 92.f},
    {10.f, 14.f, 16.f, 22.f, 37.f, 55.f, 78.f, 95.f},
    {16.f, 19.f, 24.f, 29.f, 56.f, 64.f, 87.f, 98.f},
    {24.f, 26.f, 40.f, 51.f, 68.f, 81.f, 103.f, 112.f},
    {40.f, 58.f, 57.f, 87.f, 109.f, 104.f, 121.f, 100.f},
    {51.f, 60.f, 69.f, 80.f, 103.f, 113.f, 120.f, 103.f},
    {61.f, 55.f, 56.f, 62.f, 77.f, 92.f, 101.f, 99.f}
};

__device__ const float QTinv[8][8] = {
    {1.f/16.f, 1.f/12.f, 1.f/14.f, 1.f/14.f, 1.f/18.f, 1.f/24.f, 1.f/49.f, 1.f/72.f},
    {1.f/11.f, 1.f/12.f, 1.f/13.f, 1.f/17.f, 1.f/22.f, 1.f/35.f, 1.f/64.f, 1.f/92.f},
    {1.f/10.f, 1.f/14.f, 1.f/16.f, 1.f/22.f, 1.f/37.f, 1.f/55.f, 1.f/78.f, 1.f/95.f},
    {1.f/16.f, 1.f/19.f, 1.f/24.f, 1.f/29.f, 1.f/56.f, 1.f/64.f, 1.f/87.f, 1.f/98.f},
    {1.f/24.f, 1.f/26.f, 1.f/40.f, 1.f/51.f, 1.f/68.f, 1.f/81.f, 1.f/103.f, 1.f/112.f},
    {1.f/40.f, 1.f/58.f, 1.f/57.f, 1.f/87.f, 1.f/109.f, 1.f/104.f, 1.f/121.f, 1.f/100.f},
    {1.f/51.f, 1.f/60.f, 1.f/69.f, 1.f/80.f, 1.f/103.f, 1.f/113.f, 1.f/120.f, 1.f/103.f},
    {1.f/61.f, 1.f/55.f, 1.f/56.f, 1.f/62.f, 1.f/77.f, 1.f/92.f, 1.f/101.f, 1.f/99.f}
};

constexpr int W = 512;
constexpr int N_THREADS_TOTAL = 32 * 3 * 64 * 64 * 8;  // 8 lanes per 8x8 block
constexpr float RNDC = 12582912.0f;                    // 1.5 * 2^23

// Forward 8-point DCT-II on 8 contiguous registers (even/odd folded, 40 ops).
__device__ __forceinline__ void fwd8(float* __restrict__ v) {
    float s[4], d[4];
#pragma unroll
    for (int k = 0; k < 4; ++k) {
        s[k] = v[k] + v[7 - k];
        d[k] = v[k] - v[7 - k];
    }
#pragma unroll
    for (int m = 0; m < 4; ++m) {
        float a = Dm[2 * m][0] * s[0];
        float b = Dm[2 * m + 1][0] * d[0];
#pragma unroll
        for (int k = 1; k < 4; ++k) {
            a = fmaf(Dm[2 * m][k], s[k], a);
            b = fmaf(Dm[2 * m + 1][k], d[k], b);
        }
        v[2 * m] = a;
        v[2 * m + 1] = b;
    }
}

// Inverse 8-point (DCT-III): y[j] = sum_i D[i][j] v[i], even/odd folded.
__device__ __forceinline__ void inv8(float* __restrict__ v) {
    float E[4], O[4];
#pragma unroll
    for (int j = 0; j < 4; ++j) {
        float e = Dm[0][j] * v[0];
        float o = Dm[1][j] * v[1];
#pragma unroll
        for (int m = 1; m < 4; ++m) {
            e = fmaf(Dm[2 * m][j], v[2 * m], e);
            o = fmaf(Dm[2 * m + 1][j], v[2 * m + 1], o);
        }
        E[j] = e;
        O[j] = o;
    }
#pragma unroll
    for (int j = 0; j < 4; ++j) {
        v[j] = E[j] + O[j];
        v[7 - j] = E[j] - O[j];
    }
}

// 8x8 transpose across 8 lanes (lane = row, reg index = col).
// Stage m exchanges bit m between lane index and register index.
__device__ __forceinline__ void transpose8(float* __restrict__ x, int lane) {
#pragma unroll
    for (int m = 4; m >= 1; m >>= 1) {
        const bool up = (lane & m) != 0;
#pragma unroll
        for (int j = 0; j < 8; ++j) {
            if ((j & m) == 0) {
                float send = up ? x[j] : x[j + m];
                float got = __shfl_xor_sync(0xffffffffu, send, m);
                if (up) x[j] = got; else x[j + m] = got;
            }
        }
    }
}

} // namespace

__global__ void __launch_bounds__(256)
diffjpeg_kernel(const float* __restrict__ in, float* __restrict__ out) {
    const int t = blockIdx.x * 256 + threadIdx.x;
    const int lane = t & 7;          // row within the 8x8 block
    const int blk = t >> 3;
    const int bx = blk & 63;
    const int by = (blk >> 6) & 63;
    const int bc = blk >> 12;        // fused batch*channel, 0..95

    const size_t off = ((size_t)bc * W + (size_t)by * 8 + lane) * W + (size_t)bx * 8;

    // ---- load this lane's row (8 floats) ----
    float4 a = __ldg((const float4*)(in + off));
    float4 b = __ldg((const float4*)(in + off + 4));
    float X[8] = {a.x, a.y, a.z, a.w, b.x, b.y, b.z, b.w};

    // ---- per-lane quant tables: Q^T[lane][*] (L1-hot) ----
    float4 qa = __ldg((const float4*)(&QTq[lane][0]));
    float4 qb = __ldg((const float4*)(&QTq[lane][4]));
    float4 ia = __ldg((const float4*)(&QTinv[lane][0]));
    float4 ib = __ldg((const float4*)(&QTinv[lane][4]));
    const float Qv[8]  = {qa.x, qa.y, qa.z, qa.w, qb.x, qb.y, qb.z, qb.w};
    const float Qiv[8] = {ia.x, ia.y, ia.z, ia.w, ib.x, ib.y, ib.z, ib.w};

    // ---- forward DCT: row transform, transpose, row transform (=columns) ----
    fwd8(X);
    transpose8(X, lane);
    fwd8(X);
    // now X[i] = DCT coeff [i][lane]

    // ---- quantize/dequantize (round-to-nearest-even via magic constant) ----
#pragma unroll
    for (int i = 0; i < 8; ++i) {
        float r = __fadd_rn(__fmaf_rn(X[i], Qiv[i], RNDC), -RNDC);
        X[i] = r * Qv[i];
    }

    // ---- inverse DCT ----
    inv8(X);
    transpose8(X, lane);
    inv8(X);
    // X = reconstructed row `lane`

    // ---- store ----
    *(float4*)(out + off)     = make_float4(X[0], X[1], X[2], X[3]);
    *(float4*)(out + off + 4) = make_float4(X[4], X[5], X[6], X[7]);
}

extern "C" void kernel_launch(void* const* d_in, const int* in_sizes, int n_in,
                              void* d_out, int out_size) {
    const float* img = (const float*)d_in[0];
    float* out = (float*)d_out;
    (void)in_sizes; (void)n_in; (void)out_size;

    const int threads = 256;
    const int blocks = N_THREADS_TOTAL / threads;  // 12288
    diffjpeg_kernel<<<blocks, threads>>>(img, out);
}